// round 3
// baseline (speedup 1.0000x reference)
#include <cuda_runtime.h>

// FlowNetC correlation, specialized for B=4, C=128, H=W=96,
// max_displacement=20, stride2=2 (21x21 displacements), K=1, S1=1.
//
// out[b, iy*21+ix, y, x] = (1/128) * sum_c in1[b,c,y,x] * in2[b,c,y+dy,x+dx]
//   dy = (iy-10)*2, dx = (ix-10)*2, zero outside [0,96).

#define CORR_B 4
#define CORR_C 128
#define CORR_H 96
#define CORR_W 96
#define ND 21            // displacements per axis
#define NDD (ND*ND)      // 441
#define DYG 3            // dy rows resident per phase
#define PHASES 7         // 21 / 3
#define CCK 32           // channel chunk for K rows
#define NCHUNK 4         // 128 / 32
#define QSTRIDE 100      // padded Q row stride (floats)
#define KXDIM 140        // padded K row: [0..19]=0, [20..115]=data, [116..139]=0
#define KROW (CCK*KXDIM + 4)   // per-dy-row stride (floats), +4 bank stagger
#define NTHREADS 128
#define NACTIVE 108      // 3 dyg * 3 dxg * 12 xg
#define SMEM_FLOATS (CORR_C*QSTRIDE + DYG*KROW)
#define SMEM_BYTES (SMEM_FLOATS*4)

__global__ void __launch_bounds__(NTHREADS, 2)
corr_kernel(const float* __restrict__ in1, const float* __restrict__ in2,
            float* __restrict__ out)
{
    extern __shared__ float smem[];
    float* Qs = smem;                       // [128][QSTRIDE]
    float* Ks = smem + CORR_C * QSTRIDE;    // [DYG][CCK][KXDIM] (+stagger)

    const int y   = blockIdx.x;
    const int b   = blockIdx.y;
    const int tid = threadIdx.x;

    // ---- Load Q = in1[b, :, y, :] (once per block), float4, coalesced ----
    {
        const float* src = in1 + ((size_t)b * CORR_C * CORR_H + y) * CORR_W;
        #pragma unroll 4
        for (int i = tid; i < CORR_C * (CORR_W / 4); i += NTHREADS) {
            int c  = i / (CORR_W / 4);
            int xq = i - c * (CORR_W / 4);
            float4 v = *(const float4*)(src + (size_t)c * CORR_H * CORR_W + xq * 4);
            *(float4*)(Qs + c * QSTRIDE + xq * 4) = v;
        }
    }
    // ---- Zero all K rows once: pads stay zero forever after ----
    for (int i = tid; i < DYG * KROW; i += NTHREADS) Ks[i] = 0.0f;

    // ---- Thread tile: (dyg, dxg, xg) -> 7 dx x 8 x outputs for one dy ----
    const bool active = tid < NACTIVE;
    int dyg = 0, dxg = 0, xg = 0;
    if (active) {
        dyg = tid / 36;
        int r = tid - dyg * 36;
        dxg = r / 12;
        xg  = r - dxg * 12;
    }
    const int x0 = xg * 8;
    // padded k index for (x, dx): (x+dx)+20 = x0 + i + 14*dxg + 2*j
    const float* kthread = Ks + dyg * KROW + (x0 + 14 * dxg);

    for (int p = 0; p < PHASES; ++p) {
        float acc[7][8];
        #pragma unroll
        for (int j = 0; j < 7; ++j)
            #pragma unroll
            for (int i = 0; i < 8; ++i) acc[j][i] = 0.0f;

        for (int cc = 0; cc < NCHUNK; ++cc) {
            __syncthreads();   // prior phase/chunk consumers done before overwrite
            // ---- Load K interior: 3 dy rows x 32 ch x 96 floats (float4) ----
            #pragma unroll 2
            for (int i = tid; i < DYG * CCK * (CORR_W / 4); i += NTHREADS) {
                int r   = i / (CCK * (CORR_W / 4));
                int rem = i - r * (CCK * (CORR_W / 4));
                int c   = rem / (CORR_W / 4);
                int xq  = rem - c * (CORR_W / 4);
                int diy = p * DYG + r;
                int yy  = y + (diy - 10) * 2;
                float4 v = make_float4(0.f, 0.f, 0.f, 0.f);
                if ((unsigned)yy < CORR_H)
                    v = *(const float4*)(in2 +
                        (((size_t)b * CORR_C + (cc * CCK + c)) * CORR_H + yy) * CORR_W + xq * 4);
                *(float4*)(Ks + r * KROW + c * KXDIM + 20 + xq * 4) = v;
            }
            __syncthreads();

            if (active) {
                const float* qb = Qs + cc * CCK * QSTRIDE + x0;
                #pragma unroll 2
                for (int c = 0; c < CCK; ++c) {
                    float4 q0 = *(const float4*)(qb + c * QSTRIDE);
                    float4 q1 = *(const float4*)(qb + c * QSTRIDE + 4);
                    float q[8] = {q0.x, q0.y, q0.z, q0.w, q1.x, q1.y, q1.z, q1.w};
                    float kf[20];
                    const float2* kp = (const float2*)(kthread + c * KXDIM);
                    #pragma unroll
                    for (int t = 0; t < 10; ++t) {
                        float2 kv = kp[t];
                        kf[2 * t]     = kv.x;
                        kf[2 * t + 1] = kv.y;
                    }
                    #pragma unroll
                    for (int j = 0; j < 7; ++j)
                        #pragma unroll
                        for (int i = 0; i < 8; ++i)
                            acc[j][i] += q[i] * kf[i + 2 * j];
                }
            }
        }

        // ---- Store this phase's outputs (invalid dy rows are zeros) ----
        if (active) {
            const int diy = p * DYG + dyg;
            const float s = 1.0f / 128.0f;
            #pragma unroll
            for (int j = 0; j < 7; ++j) {
                int d = diy * ND + dxg * 7 + j;
                float* o = out + (((size_t)b * NDD + d) * CORR_H + y) * CORR_W + x0;
                float4 v0 = make_float4(acc[j][0] * s, acc[j][1] * s,
                                        acc[j][2] * s, acc[j][3] * s);
                float4 v1 = make_float4(acc[j][4] * s, acc[j][5] * s,
                                        acc[j][6] * s, acc[j][7] * s);
                *(float4*)(o)     = v0;
                *(float4*)(o + 4) = v1;
            }
        }
    }
}

extern "C" void kernel_launch(void* const* d_in, const int* in_sizes, int n_in,
                              void* d_out, int out_size)
{
    const float* in1 = (const float*)d_in[0];
    const float* in2 = (const float*)d_in[1];
    float* out = (float*)d_out;

    cudaFuncSetAttribute(corr_kernel,
                         cudaFuncAttributeMaxDynamicSharedMemorySize, SMEM_BYTES);
    corr_kernel<<<dim3(CORR_H, CORR_B), NTHREADS, SMEM_BYTES>>>(in1, in2, out);
}

// round 5
// speedup vs baseline: 2.4518x; 2.4518x over previous
#include <cuda_runtime.h>

// FlowNetC correlation, specialized: B=4, C=128, H=W=96, md=20, stride2=2,
// K=1, S1=1  ->  out[b, iy*21+ix, y, x] = (1/128)*sum_c in1[b,c,y,x]*in2[b,c,y+dy,x+dx]
// dy=(iy-10)*2, dx=(ix-10)*2, zero outside [0,96).

#define ND 21
#define NDD 441
#define CH 128
#define HH 96
#define WW 96
#define DYG 7            // dy rows per block (phase)
#define CCK 8            // channels per K chunk
#define NCHUNK 16        // 128/8
#define QSTRIDE 100      // Q row stride (floats)
#define KX 140           // padded K row: [0..19]=0, [20..115]=data, [116..139]=0
#define KROW (CCK*KX + 4)
#define NT 256
#define NACT 252         // 7 dyg * 3 dxg * 12 xg
#define SMEMF (CH*QSTRIDE + DYG*KROW)
#define SMEMB (SMEMF*4)

__global__ void __launch_bounds__(NT, 2)
corr_kernel(const float* __restrict__ in1, const float* __restrict__ in2,
            float* __restrict__ out)
{
    extern __shared__ float smem[];
    float* Qs = smem;                 // [128][QSTRIDE]
    float* Ks = smem + CH * QSTRIDE;  // [DYG][CCK][KX] (+stagger per dy row)

    const int y   = blockIdx.x;
    const int b   = blockIdx.y;
    const int p   = blockIdx.z;       // dy phase: rows p*7 .. p*7+6
    const int tid = threadIdx.x;

    // ---- Load Q = in1[b, :, y, :] (float4, lanes consecutive -> coalesced) ----
    {
        const float* src = in1 + ((size_t)b * CH * HH + y) * WW;
        #pragma unroll 4
        for (int i = tid; i < CH * (WW / 4); i += NT) {
            int c  = i / (WW / 4);
            int xq = i - c * (WW / 4);
            float4 v = *(const float4*)(src + (size_t)c * HH * WW + xq * 4);
            *(float4*)(Qs + c * QSTRIDE + xq * 4) = v;
        }
    }
    // ---- Zero K pads once (interior rewritten every chunk) ----
    for (int i = tid; i < DYG * KROW; i += NT) Ks[i] = 0.0f;

    // ---- Thread tile: (dyg, dxg, xg); x half-split {4xg..+3} U {4xg+48..+51} ----
    const bool active = tid < NACT;
    int dyg = 0, dxg = 0, xg = 0;
    if (active) {
        dyg = tid / 36;
        int r = tid - dyg * 36;
        dxg = r / 12;
        xg  = r - dxg * 12;
    }
    const int xA   = 4 * xg;             // half-A x base (half-B = xA+48)
    const int koff = 4 * xg + 14 * dxg;  // k float offset for (x=4xg, j=0, i=0)

    float acc[7][8];
    #pragma unroll
    for (int j = 0; j < 7; ++j)
        #pragma unroll
        for (int i = 0; i < 8; ++i) acc[j][i] = 0.0f;

    for (int cc = 0; cc < NCHUNK; ++cc) {
        __syncthreads();   // previous chunk fully consumed
        // ---- Load K interior: 7 dy rows x 8 ch x 96 floats (float4) ----
        #pragma unroll 2
        for (int i = tid; i < DYG * CCK * (WW / 4); i += NT) {
            int r   = i / (CCK * (WW / 4));
            int rem = i - r * (CCK * (WW / 4));
            int c   = rem / (WW / 4);
            int xq  = rem - c * (WW / 4);
            int yy  = y + (p * DYG + r - 10) * 2;
            float4 v = make_float4(0.f, 0.f, 0.f, 0.f);
            if ((unsigned)yy < HH)
                v = *(const float4*)(in2 +
                    (((size_t)b * CH + (cc * CCK + c)) * HH + yy) * WW + xq * 4);
            *(float4*)(Ks + r * KROW + c * KX + 20 + xq * 4) = v;
        }
        __syncthreads();

        if (active) {
            #pragma unroll 2
            for (int c = 0; c < CCK; ++c) {
                const float* qrow = Qs + (cc * CCK + c) * QSTRIDE;
                const float* krow = Ks + dyg * KROW + c * KX + koff;
                #pragma unroll
                for (int h = 0; h < 2; ++h) {
                    float4 q = *(const float4*)(qrow + xA + 48 * h);
                    float kf[16];
                    const float2* kp = (const float2*)(krow + 48 * h);
                    #pragma unroll
                    for (int u = 0; u < 8; ++u) {
                        float2 v = kp[u];
                        kf[2 * u]     = v.x;
                        kf[2 * u + 1] = v.y;
                    }
                    #pragma unroll
                    for (int j = 0; j < 7; ++j) {
                        acc[j][4 * h + 0] += q.x * kf[2 * j + 0];
                        acc[j][4 * h + 1] += q.y * kf[2 * j + 1];
                        acc[j][4 * h + 2] += q.z * kf[2 * j + 2];
                        acc[j][4 * h + 3] += q.w * kf[2 * j + 3];
                    }
                }
            }
        }
    }

    // ---- Store: 7 dx x (two float4 halves) for this thread's dy ----
    if (active) {
        const int diy = p * DYG + dyg;
        const float s = 1.0f / 128.0f;
        #pragma unroll
        for (int j = 0; j < 7; ++j) {
            int d = diy * ND + dxg * 7 + j;
            float* o = out + (((size_t)b * NDD + d) * HH + y) * WW;
            float4 v0 = make_float4(acc[j][0] * s, acc[j][1] * s,
                                    acc[j][2] * s, acc[j][3] * s);
            float4 v1 = make_float4(acc[j][4] * s, acc[j][5] * s,
                                    acc[j][6] * s, acc[j][7] * s);
            *(float4*)(o + xA)      = v0;
            *(float4*)(o + xA + 48) = v1;
        }
    }
}

extern "C" void kernel_launch(void* const* d_in, const int* in_sizes, int n_in,
                              void* d_out, int out_size)
{
    const float* in1 = (const float*)d_in[0];
    const float* in2 = (const float*)d_in[1];
    float* out = (float*)d_out;

    cudaFuncSetAttribute(corr_kernel,
                         cudaFuncAttributeMaxDynamicSharedMemorySize, SMEMB);
    corr_kernel<<<dim3(HH, 4, 3), NT, SMEMB>>>(in1, in2, out);
}

// round 6
// speedup vs baseline: 3.2956x; 1.3441x over previous
#include <cuda_runtime.h>

// FlowNetC correlation: B=4, C=128, H=W=96, md=20, stride2=2, K=1, S1=1.
// out[b, iy*21+ix, y, x] = (1/128)*sum_c in1[b,c,y,x]*in2[b,c,y+dy,x+dx]
// dy=(iy-10)*2, dx=(ix-10)*2, zero outside [0,96).
//
// Block = (y, b, dy-phase of 7). Per chunk of 8 channels: Q row chunk + 7
// zero-padded K rows in smem, K stored TWICE (copy B shifted left 2 floats)
// so every thread's 16-float k window is float4-aligned in one copy.

#define ND 21
#define NDD 441
#define CH 128
#define HH 96
#define WW 96
#define DYG 7
#define CCK 8
#define NCHUNK 16
#define QST 96
#define KX 144               // padded K row: [0..19]=0, [20..115]=data, rest 0
#define KROW (CCK*KX + 4)    // 1156 floats -> 289 groups == 1 mod 8 (dyg slot spread)
#define ABASE 768            // copy A base (floats); group 192 == 0 mod 8
#define BBASE 8872           // copy B base; group 2218 == 2 mod 8 (dxg slot spread)
#define SMEMF (BBASE + DYG*KROW)   // 16964 floats
#define SMEMB (SMEMF*4)
#define NT 256
#define NACT 252             // 7 dyg * 3 dxg * 12 xg

__global__ void __launch_bounds__(NT, 2)
corr_kernel(const float* __restrict__ in1, const float* __restrict__ in2,
            float* __restrict__ out)
{
    extern __shared__ float smem[];
    float* Qs = smem;           // [8][96]
    float* KsA = smem + ABASE;  // [7][8][144] (+4 stagger per dy row)
    float* KsB = smem + BBASE;  // same, elements shifted: B[i] = element(i+2)

    const int y   = blockIdx.x;
    const int b   = blockIdx.y;
    const int p   = blockIdx.z;       // dy rows p*7 .. p*7+6
    const int tid = threadIdx.x;

    // Zero K pads once (interior rewritten every chunk; pads stay zero)
    for (int i = tid; i < SMEMF - ABASE; i += NT) smem[ABASE + i] = 0.0f;

    // Thread tile: (dyg, dxg, xg); x = {4xg..4xg+3} U {4xg+48..51}
    const bool active = tid < NACT;
    int dyg = 0, dxg = 0, xg = 0;
    if (active) {
        dyg = tid / 36;
        int r = tid - dyg * 36;
        dxg = r / 12;
        xg  = r - dxg * 12;
    }
    const int xA   = 4 * xg;
    const int koff = 4 * xg + 14 * dxg;          // always even
    // parity-select copy: koff%4==0 -> A, ==2 -> B (B[-2] maps element koff)
    const float* kthr = ((koff & 2) ? (KsB - 2) : KsA) + dyg * KROW + koff;

    float acc[7][8];
    #pragma unroll
    for (int j = 0; j < 7; ++j)
        #pragma unroll
        for (int i = 0; i < 8; ++i) acc[j][i] = 0.0f;

    for (int cc = 0; cc < NCHUNK; ++cc) {
        __syncthreads();   // previous chunk fully consumed
        // ---- Load: 192 Q float4 + 1344 K float4 = 6 tasks/thread ----
        #pragma unroll
        for (int it = 0; it < 6; ++it) {
            int i = tid + it * NT;
            if (i < 192) {
                int c  = i / 24;
                int xq = i - c * 24;
                float4 v = *(const float4*)(in1 +
                    (((size_t)b * CH + cc * CCK + c) * HH + y) * WW + xq * 4);
                *(float4*)(Qs + c * QST + xq * 4) = v;
            } else {
                int t   = i - 192;
                int r   = t / 192;
                int rem = t - r * 192;
                int c   = rem / 24;
                int xq  = rem - c * 24;
                int yy  = y + (p * DYG + r - 10) * 2;
                float4 v = make_float4(0.f, 0.f, 0.f, 0.f);
                if ((unsigned)yy < HH)
                    v = *(const float4*)(in2 +
                        (((size_t)b * CH + cc * CCK + c) * HH + yy) * WW + xq * 4);
                int e = 20 + 4 * xq;
                float* ra = KsA + r * KROW + c * KX;
                float* rb = KsB + r * KROW + c * KX;
                *(float4*)(ra + e) = v;
                *(float2*)(rb + e - 2) = make_float2(v.x, v.y);  // B[e-2]=elem e
                *(float2*)(rb + e)     = make_float2(v.z, v.w);  // B[e]=elem e+2
            }
        }
        __syncthreads();

        if (active) {
            #pragma unroll 2
            for (int c = 0; c < CCK; ++c) {
                const float* qrow = Qs + c * QST + xA;
                const float* krow = kthr + c * KX;
                #pragma unroll
                for (int h = 0; h < 2; ++h) {
                    float4 q  = *(const float4*)(qrow + 48 * h);
                    float4 k0 = *(const float4*)(krow + 48 * h);
                    float4 k1 = *(const float4*)(krow + 48 * h + 4);
                    float4 k2 = *(const float4*)(krow + 48 * h + 8);
                    float4 k3 = *(const float4*)(krow + 48 * h + 12);
                    float kw[16] = {k0.x, k0.y, k0.z, k0.w,
                                    k1.x, k1.y, k1.z, k1.w,
                                    k2.x, k2.y, k2.z, k2.w,
                                    k3.x, k3.y, k3.z, k3.w};
                    #pragma unroll
                    for (int j = 0; j < 7; ++j) {
                        acc[j][4 * h + 0] += q.x * kw[2 * j + 0];
                        acc[j][4 * h + 1] += q.y * kw[2 * j + 1];
                        acc[j][4 * h + 2] += q.z * kw[2 * j + 2];
                        acc[j][4 * h + 3] += q.w * kw[2 * j + 3];
                    }
                }
            }
        }
    }

    if (active) {
        const int diy = p * DYG + dyg;
        const float s = 1.0f / 128.0f;
        #pragma unroll
        for (int j = 0; j < 7; ++j) {
            int d = diy * ND + dxg * 7 + j;
            float* o = out + (((size_t)b * NDD + d) * HH + y) * WW;
            float4 v0 = make_float4(acc[j][0] * s, acc[j][1] * s,
                                    acc[j][2] * s, acc[j][3] * s);
            float4 v1 = make_float4(acc[j][4] * s, acc[j][5] * s,
                                    acc[j][6] * s, acc[j][7] * s);
            *(float4*)(o + xA)      = v0;
            *(float4*)(o + xA + 48) = v1;
        }
    }
}

extern "C" void kernel_launch(void* const* d_in, const int* in_sizes, int n_in,
                              void* d_out, int out_size)
{
    const float* in1 = (const float*)d_in[0];
    const float* in2 = (const float*)d_in[1];
    float* out = (float*)d_out;

    cudaFuncSetAttribute(corr_kernel,
                         cudaFuncAttributeMaxDynamicSharedMemorySize, SMEMB);
    corr_kernel<<<dim3(HH, 4, 3), NT, SMEMB>>>(in1, in2, out);
}